// round 3
// baseline (speedup 1.0000x reference)
#include <cuda_runtime.h>

// Problem constants
#define HH   512
#define WW   512
#define BB   4
#define CINC 55
#define NRr  30
#define NCc  20
#define NCELL 600
#define OUTX 57671680   // 4*55*512*512

// Scratch (device globals; no allocation)
__device__ float g_Stop[NCELL];
__device__ float g_Sbot[NCELL];
__device__ float g_topm[NCELL];
__device__ float g_sig[NCELL];
__device__ float g_wtsum[18];
__device__ float g_btsum;

// ---------------------------------------------------------------------------
// Kernel 1: zero accumulators, fold the 36-ch top head into an 18-vector.
// top is mean'ed over channels, so only sum_c wt[c,:] and sum_c bt[c] matter.
// ---------------------------------------------------------------------------
__global__ __launch_bounds__(640) void prep_kernel(const float* __restrict__ wt,
                                                   const float* __restrict__ bt) {
    int t = threadIdx.x;
    if (t < NCELL) { g_Stop[t] = 0.f; g_Sbot[t] = 0.f; }
    if (t < 18) {
        float s = 0.f;
        #pragma unroll 4
        for (int c = 0; c < 36; c++) s += wt[c * 18 + t];
        g_wtsum[t] = s;
    }
    if (t == 0) {
        float s = 0.f;
        for (int c = 0; c < 36; c++) s += bt[c];
        g_btsum = s;
    }
}

// ---------------------------------------------------------------------------
// Kernel 2: fused 3x dilated 5x5 conv (55->18) + ReLU + feat store +
//           per-cell accumulation of channel-summed top and bot heads.
// Tile: 32x32 output pixels per block, 256 threads (32x8), 4 pixels/thread.
// ---------------------------------------------------------------------------
__global__ __launch_bounds__(256, 2) void conv_kernel(
    const float* __restrict__ x,
    const int*   __restrict__ row_seg,
    const int*   __restrict__ col_seg,
    const float* __restrict__ w1, const float* __restrict__ b1,
    const float* __restrict__ w2, const float* __restrict__ b2,
    const float* __restrict__ w3, const float* __restrict__ b3,
    const float* __restrict__ wbv, const float* __restrict__ bbv,
    float* __restrict__ out)
{
    __shared__ float tile[44 * 44];     // 32x32 tile + halo 6 each side
    __shared__ float sw[456];           // per-channel weights: 3 convs * 6 out * 25 taps
    __shared__ float sbias[18];
    __shared__ float swt[18], swb[18];
    __shared__ float sbt, sbb;
    __shared__ float cT[NCELL], cB[NCELL];

    const int tid = threadIdx.x;
    const int tx = tid & 31;
    const int ty = tid >> 5;
    const int gx0 = blockIdx.x * 32;
    const int gy0 = blockIdx.y * 32;
    const int b   = blockIdx.z;

    for (int t = tid; t < NCELL; t += 256) { cT[t] = 0.f; cB[t] = 0.f; }
    if (tid < 6) {
        sbias[tid]      = b1[tid];
        sbias[6 + tid]  = b2[tid];
        sbias[12 + tid] = b3[tid];
    }
    if (tid < 18) { swt[tid] = g_wtsum[tid]; swb[tid] = wbv[tid]; }
    if (tid == 0) { sbt = g_btsum; sbb = bbv[0]; }

    float acc[4][18];
    #pragma unroll
    for (int p = 0; p < 4; p++)
        #pragma unroll
        for (int j = 0; j < 18; j++) acc[p][j] = 0.f;

    const float* wp0 = w1;
    const float* wp1 = w2;
    const float* wp2 = w3;

    for (int c = 0; c < CINC; c++) {
        // stage per-channel weights: sw[d*150 + o*25 + k] = wX[o][c][k]
        for (int t = tid; t < 450; t += 256) {
            int d = t / 150, r = t - d * 150;
            int o = r / 25,  k = r - o * 25;
            const float* wp = (d == 0) ? wp0 : (d == 1 ? wp1 : wp2);
            sw[d * 150 + o * 25 + k] = wp[(o * 55 + c) * 25 + k];
        }
        // stage input tile with halo (zero-pad outside image)
        const float* xc = x + (((size_t)(b * CINC + c)) << 18);
        for (int t = tid; t < 44 * 44; t += 256) {
            int rr = t / 44, cc = t - rr * 44;
            int gy = gy0 - 6 + rr;
            int gx = gx0 - 6 + cc;
            float v = 0.f;
            if ((unsigned)gy < 512u && (unsigned)gx < 512u)
                v = xc[(gy << 9) + gx];
            tile[t] = v;
        }
        __syncthreads();

        #pragma unroll
        for (int ky = 0; ky < 5; ky++) {
            #pragma unroll
            for (int kx = 0; kx < 5; kx++) {
                const int k = ky * 5 + kx;
                float wA[6], wB[6], wC[6];
                #pragma unroll
                for (int o = 0; o < 6; o++) {
                    wA[o] = sw[o * 25 + k];
                    wB[o] = sw[150 + o * 25 + k];
                    wC[o] = sw[300 + o * 25 + k];
                }
                #pragma unroll
                for (int p = 0; p < 4; p++) {
                    const int yy = ty + p * 8 + 6;
                    const int xb = tx + 6;
                    float s1 = tile[(yy + (ky - 2)) * 44 + xb + (kx - 2)];
                    float s2 = tile[(yy + 2 * (ky - 2)) * 44 + xb + 2 * (kx - 2)];
                    float s3 = tile[(yy + 3 * (ky - 2)) * 44 + xb + 3 * (kx - 2)];
                    #pragma unroll
                    for (int o = 0; o < 6; o++) {
                        acc[p][o]      = fmaf(s1, wA[o], acc[p][o]);
                        acc[p][6 + o]  = fmaf(s2, wB[o], acc[p][6 + o]);
                        acc[p][12 + o] = fmaf(s3, wC[o], acc[p][12 + o]);
                    }
                }
            }
        }
        __syncthreads();
    }

    // epilogue: bias+relu, store feat (channels 36..53), cell accumulation
    const int gx = gx0 + tx;
    const int cs = col_seg[gx];
    #pragma unroll
    for (int p = 0; p < 4; p++) {
        const int gy = gy0 + ty + p * 8;
        const int cell = row_seg[gy] * NCc + cs;
        float st = sbt, sb = sbb;
        const unsigned pixoff = ((unsigned)gy << 9) + (unsigned)gx;
        #pragma unroll
        for (int j = 0; j < 18; j++) {
            float f = fmaxf(acc[p][j] + sbias[j], 0.f);
            out[(((unsigned)(b * CINC + 36 + j)) << 18) + pixoff] = f;
            st = fmaf(swt[j], f, st);
            sb = fmaf(swb[j], f, sb);
        }
        atomicAdd(&cT[cell], st);
        atomicAdd(&cB[cell], sb);
    }
    __syncthreads();
    for (int t = tid; t < NCELL; t += 256) {
        float v0 = cT[t], v1 = cB[t];
        if (v0 != 0.f) atomicAdd(&g_Stop[t], v0);
        if (v1 != 0.f) atomicAdd(&g_Sbot[t], v1);
    }
}

// ---------------------------------------------------------------------------
// Kernel 3: finalize means -> top_m, sigmoid(bot_m); write pools output.
// ---------------------------------------------------------------------------
__global__ __launch_bounds__(640) void finalize_kernel(
    const int* __restrict__ row_seg, const int* __restrict__ col_seg,
    float* __restrict__ out)
{
    __shared__ int rc[NRr];
    __shared__ int cc[NCc];
    int t = threadIdx.x;
    if (t < NRr) rc[t] = 0;
    if (t < NCc) cc[t] = 0;
    __syncthreads();
    if (t < 512) {
        atomicAdd(&rc[row_seg[t]], 1);
        atomicAdd(&cc[col_seg[t]], 1);
    }
    __syncthreads();
    if (t < NCELL) {
        int r = t / NCc, c = t - r * NCc;
        float pix = (float)(rc[r] * cc[c]);
        float tm = g_Stop[t] / (pix * (float)(BB * 36));
        float bm = g_Sbot[t] / (pix * (float)BB);
        g_topm[t] = tm;
        float sg = 1.f / (1.f + expf(-bm));
        g_sig[t] = sg;
        #pragma unroll
        for (int b = 0; b < BB; b++)
            out[OUTX + b * NCELL + t] = sg;
    }
}

// ---------------------------------------------------------------------------
// Kernel 4: broadcast fill of channels 0..35 (top_m) and 54 (sigmoid(bot_m)).
// ---------------------------------------------------------------------------
__global__ __launch_bounds__(256) void bcast_kernel(
    const int* __restrict__ row_seg, const int* __restrict__ col_seg,
    float* __restrict__ out)
{
    unsigned idx = blockIdx.x * 256u + threadIdx.x;   // (b*512+y)*512+x
    unsigned xc = idx & 511u;
    unsigned y  = (idx >> 9) & 511u;
    unsigned b  = idx >> 18;
    int cell = __ldg(&row_seg[y]) * NCc + __ldg(&col_seg[xc]);
    float tv = g_topm[cell];
    float sv = g_sig[cell];
    unsigned base = ((b * (unsigned)CINC) << 18) + (y << 9) + xc;
    #pragma unroll
    for (int ch = 0; ch < 36; ch++)
        out[base + ((unsigned)ch << 18)] = tv;
    out[base + (54u << 18)] = sv;
}

// ---------------------------------------------------------------------------
extern "C" void kernel_launch(void* const* d_in, const int* in_sizes, int n_in,
                              void* d_out, int out_size) {
    const float* x       = (const float*)d_in[0];
    const int*   row_seg = (const int*)d_in[1];
    const int*   col_seg = (const int*)d_in[2];
    const float* w1 = (const float*)d_in[3];
    const float* b1 = (const float*)d_in[4];
    const float* w2 = (const float*)d_in[5];
    const float* b2 = (const float*)d_in[6];
    const float* w3 = (const float*)d_in[7];
    const float* b3 = (const float*)d_in[8];
    const float* wt = (const float*)d_in[9];
    const float* bt = (const float*)d_in[10];
    const float* wb = (const float*)d_in[11];
    const float* bb = (const float*)d_in[12];
    float* out = (float*)d_out;

    prep_kernel<<<1, 640>>>(wt, bt);

    dim3 grid(WW / 32, HH / 32, BB);
    conv_kernel<<<grid, 256>>>(x, row_seg, col_seg,
                               w1, b1, w2, b2, w3, b3, wb, bb, out);

    finalize_kernel<<<1, 640>>>(row_seg, col_seg, out);

    bcast_kernel<<<(BB * HH * WW) / 256, 256>>>(row_seg, col_seg, out);
}